// round 12
// baseline (speedup 1.0000x reference)
#include <cuda_runtime.h>
#include <cuda_bf16.h>

// SimplePatchScorer: x (512,3,224,224) f32, W (1,768) f32, b (1,) f32
// out (512,196) f32.
//
// f = t*588 + e; t = i*16 + j; e = band*14 + wn (42 bands of 896 float4).
// row = f/768, k = f mod 768.
//
// R12 (base = R7, 55.8us):
//  (1) Row sharing via Δi=8: 128*588 = 98*768 -> rows i and i+8 share the
//      whole weight/predicate sequence, rows offset +98. Each thread runs
//      TWO float4 streams per weight fetch: weight-LDS and index-ALU per
//      byte halved, L1 wavefronts/byte -25%.
//  (2) Thread = (q e-quarter, p parity, i in 0..7, jp in 0..3): 256 thr,
//      512 CTAs -> 4096 warps (R7 level). e = q*147 + p + 2n; k steps by 2,
//      wraps 768 at most once -> same dual-accumulator predicated FMA.
//  (3) __launch_bounds__(256,3): ~85 regs so the LDG batch isn't squeezed
//      (R11 lesson: reg-starved MLP loses bandwidth).
//  (4) LDG.128 + __ldcs, doubled swizzled weight smem, <=16 shared atomics.

#define BATCH    512
#define NROWS    196
#define KLEN     768
#define IMG_F4   37632           // 3*224*224/4
#define B_OFF    448             // 8 rows * 224 floats = 448 float4
#define SW2SZ    1584            // 1536 + 1536/32
#define TPB      256

__global__ __launch_bounds__(TPB, 3)
void patch_scorer_kernel(const float* __restrict__ x,
                         const float* __restrict__ W,
                         const float* __restrict__ bias,
                         float* __restrict__ out)
{
    __shared__ float sW2s[SW2SZ];    // sW2s[a + (a>>5)] = W[a % 768], a<1536
    __shared__ float sAcc[200];      // 196 rows + pad for zero hi-flushes

    const int tid = threadIdx.x;
    const int b   = blockIdx.x;      // image

    #pragma unroll
    for (int a = tid; a < 2 * KLEN; a += TPB) {
        const int k = (a < KLEN) ? a : a - KLEN;
        sW2s[a + (a >> 5)] = W[k];
    }
    if (tid < 200) sAcc[tid] = 0.0f;
    __syncthreads();

    const int q  = tid >> 6;         // e-quarter 0..3
    const int p  = (tid >> 5) & 1;   // e parity (warp-uniform)
    const int i  = (tid >> 2) & 7;   // patch row (group A), group B = i+8
    const int jp = tid & 3;          // float4 group (j = 4jp..4jp+3)

    const int tb = i * 16 + jp * 4;  // t of element m=0 (group A)
    const int E0 = q * 147 + p;      // first e of this thread

    // per-element m: f_m = (tb+m)*588 + E0 ; row R_m, k-start a_m
    const int f0 = tb * 588 + E0;
    const int R0 = f0 / KLEN;
    const int R1 = (f0 +  588) / KLEN;
    const int R2 = (f0 + 1176) / KLEN;
    const int R3 = (f0 + 1764) / KLEN;
    int a0 = f0          - R0 * KLEN;
    int a1 = (f0 +  588) - R1 * KLEN;
    int a2 = (f0 + 1176) - R2 * KLEN;
    int a3 = (f0 + 1764) - R3 * KLEN;

    const float4* pA = (const float4*)x + (size_t)b * IMG_F4 + i * 56 + jp;
    const float4* pB = pA + B_OFF;   // rows i+8

    int band = E0 / 14;
    int wn   = E0 - band * 14;
    int off  = band * 896 + wn * 4;  // float4 offset within image
    const int trip = 74 - p;         // 74 even-e steps, 73 odd

    float lA0 = 0.f, lA1 = 0.f, lA2 = 0.f, lA3 = 0.f;
    float hA0 = 0.f, hA1 = 0.f, hA2 = 0.f, hA3 = 0.f;
    float lB0 = 0.f, lB1 = 0.f, lB2 = 0.f, lB3 = 0.f;
    float hB0 = 0.f, hB1 = 0.f, hB2 = 0.f, hB3 = 0.f;

    #pragma unroll 4
    for (int n = 0; n < trip; ++n) {
        const float4 vA = __ldcs(&pA[off]);
        const float4 vB = __ldcs(&pB[off]);

        const float w0 = sW2s[a0 + (a0 >> 5)];
        const float w1 = sW2s[a1 + (a1 >> 5)];
        const float w2 = sW2s[a2 + (a2 >> 5)];
        const float w3 = sW2s[a3 + (a3 >> 5)];

        if (a0 < KLEN) { lA0 += vA.x * w0; lB0 += vB.x * w0; }
        else           { hA0 += vA.x * w0; hB0 += vB.x * w0; }
        if (a1 < KLEN) { lA1 += vA.y * w1; lB1 += vB.y * w1; }
        else           { hA1 += vA.y * w1; hB1 += vB.y * w1; }
        if (a2 < KLEN) { lA2 += vA.z * w2; lB2 += vB.z * w2; }
        else           { hA2 += vA.z * w2; hB2 += vB.z * w2; }
        if (a3 < KLEN) { lA3 += vA.w * w3; lB3 += vB.w * w3; }
        else           { hA3 += vA.w * w3; hB3 += vB.w * w3; }

        a0 += 2; a1 += 2; a2 += 2; a3 += 2;
        off += 8;
        wn += 2;
        if (wn >= 14) { wn -= 14; off += 840; }   // next band
    }

    atomicAdd(&sAcc[R0     ], lA0);
    atomicAdd(&sAcc[R0 +  1], hA0);
    atomicAdd(&sAcc[R1     ], lA1);
    atomicAdd(&sAcc[R1 +  1], hA1);
    atomicAdd(&sAcc[R2     ], lA2);
    atomicAdd(&sAcc[R2 +  1], hA2);
    atomicAdd(&sAcc[R3     ], lA3);
    atomicAdd(&sAcc[R3 +  1], hA3);
    atomicAdd(&sAcc[R0 + 98], lB0);
    atomicAdd(&sAcc[R0 + 99], hB0);
    atomicAdd(&sAcc[R1 + 98], lB1);
    atomicAdd(&sAcc[R1 + 99], hB1);
    atomicAdd(&sAcc[R2 + 98], lB2);
    atomicAdd(&sAcc[R2 + 99], hB2);
    atomicAdd(&sAcc[R3 + 98], lB3);
    atomicAdd(&sAcc[R3 + 99], hB3);

    __syncthreads();

    if (tid < NROWS)
        out[(size_t)b * NROWS + tid] = sAcc[tid] + bias[0];
}

extern "C" void kernel_launch(void* const* d_in, const int* in_sizes, int n_in,
                              void* d_out, int out_size)
{
    const float* x  = (const float*)d_in[0];   // (512,3,224,224)
    const float* W  = (const float*)d_in[1];   // (1,768)
    const float* bv = (const float*)d_in[2];   // (1,)
    float* out = (float*)d_out;                // (512,196)

    patch_scorer_kernel<<<BATCH, TPB>>>(x, W, bv, out);
}